// round 7
// baseline (speedup 1.0000x reference)
#include <cuda_runtime.h>
#include <math.h>

// Problem dims (fixed)
#define NB 8
#define TT 8
#define LLEN 257
#define HH 16
#define CC 64
#define DD 1024
#define QQ 256
#define MROWS (NB*QQ)   // 2048

// ---------------- scratch (static device arrays; no allocation) ----------------
__device__ float g_ln  [MROWS*DD];
__device__ float g_h1  [MROWS*(DD/8)];
__device__ float g_sadj[MROWS*DD];
__device__ float g_x   [MROWS*DD];
__device__ float g_sq  [MROWS*DD];
__device__ float g_mix [MROWS*DD];
__device__ float g_s1  [MROWS*DD];
__device__ float g_hmid[MROWS*4*DD];
__device__ float g_tek [TT*DD];
__device__ float g_tev [TT*DD];

// ---------------- row LayerNorm ----------------
__global__ __launch_bounds__(256)
void ln_rows_k(const float* __restrict__ in, const float* __restrict__ w,
               const float* __restrict__ b, float* __restrict__ out)
{
    __shared__ float red[18];
    int r = blockIdx.x;
    int tid = threadIdx.x;
    int lane = tid & 31, warp = tid >> 5;
    float4 v = reinterpret_cast<const float4*>(in + (size_t)r*DD)[tid];
    float s = v.x + v.y + v.z + v.w;
    float q = v.x*v.x + v.y*v.y + v.z*v.z + v.w*v.w;
    #pragma unroll
    for (int o = 16; o; o >>= 1) {
        s += __shfl_xor_sync(0xffffffffu, s, o);
        q += __shfl_xor_sync(0xffffffffu, q, o);
    }
    if (lane == 0) { red[warp] = s; red[8+warp] = q; }
    __syncthreads();
    if (tid == 0) {
        float ss = 0.f, qs = 0.f;
        #pragma unroll
        for (int i = 0; i < 8; i++) { ss += red[i]; qs += red[8+i]; }
        red[16] = ss * (1.f/DD);
        red[17] = qs * (1.f/DD);
    }
    __syncthreads();
    float mean = red[16];
    float var  = red[17] - mean*mean;
    float rs   = rsqrtf(var + 1e-5f);
    float4 wv = reinterpret_cast<const float4*>(w)[tid];
    float4 bv = reinterpret_cast<const float4*>(b)[tid];
    float4 o4;
    o4.x = (v.x-mean)*rs*wv.x + bv.x;
    o4.y = (v.y-mean)*rs*wv.y + bv.y;
    o4.z = (v.z-mean)*rs*wv.z + bv.z;
    o4.w = (v.w-mean)*rs*wv.w + bv.w;
    reinterpret_cast<float4*>(out + (size_t)r*DD)[tid] = o4;
}

// ---------------- tf32 helpers ----------------
__device__ __forceinline__ unsigned f2tf(float x) {
    unsigned r;
    asm("cvt.rna.tf32.f32 %0, %1;" : "=r"(r) : "f"(x));
    return r;
}

__device__ __forceinline__ void mma_tf32(float* c, const unsigned* a, const unsigned* b) {
    asm volatile(
        "mma.sync.aligned.m16n8k8.row.col.f32.tf32.tf32.f32 "
        "{%0,%1,%2,%3},{%4,%5,%6,%7},{%8,%9},{%0,%1,%2,%3};"
        : "+f"(c[0]), "+f"(c[1]), "+f"(c[2]), "+f"(c[3])
        : "r"(a[0]), "r"(a[1]), "r"(a[2]), "r"(a[3]), "r"(b[0]), "r"(b[1]));
}

// ---------------- tf32 tensor-core GEMM: C(M,N) = A(M,K) @ W(N,K)^T ----------------
template<int EPI>
__global__ __launch_bounds__(256, 2)
void tgemm(const float* __restrict__ A, const float* __restrict__ W,
           const float* __restrict__ bias, const float* __restrict__ res,
           float* __restrict__ C, int M, int N, int K, float scale)
{
    __shared__ unsigned As[2][128][20];
    __shared__ unsigned Bs[2][128][20];

    int tid = threadIdx.x;
    int m0 = blockIdx.y * 128, n0 = blockIdx.x * 128;
    int warp = tid >> 5, lane = tid & 31;
    int wm = warp & 1, wn = warp >> 1;
    int lr = lane >> 2;
    int lc = lane & 3;

    int row = tid >> 2;
    int k4  = (tid & 3) * 4;

    const float* Ap0 = A + (size_t)(m0+row)*K + k4;
    const float* Ap1 = A + (size_t)(m0+row+64)*K + k4;
    const float* Wp0 = W + (size_t)(n0+row)*K + k4;
    const float* Wp1 = W + (size_t)(n0+row+64)*K + k4;

    float4 pa0 = *(const float4*)Ap0;
    float4 pa1 = *(const float4*)Ap1;
    float4 pw0 = *(const float4*)Wp0;
    float4 pw1 = *(const float4*)Wp1;

    float acc[4][4][4];
    #pragma unroll
    for (int mi = 0; mi < 4; mi++)
        #pragma unroll
        for (int ni = 0; ni < 4; ni++)
            #pragma unroll
            for (int f = 0; f < 4; f++) acc[mi][ni][f] = 0.f;

    {
        uint4 ua0 = make_uint4(f2tf(pa0.x), f2tf(pa0.y), f2tf(pa0.z), f2tf(pa0.w));
        uint4 ua1 = make_uint4(f2tf(pa1.x), f2tf(pa1.y), f2tf(pa1.z), f2tf(pa1.w));
        uint4 uw0 = make_uint4(f2tf(pw0.x), f2tf(pw0.y), f2tf(pw0.z), f2tf(pw0.w));
        uint4 uw1 = make_uint4(f2tf(pw1.x), f2tf(pw1.y), f2tf(pw1.z), f2tf(pw1.w));
        *(uint4*)&As[0][row][k4]    = ua0;
        *(uint4*)&As[0][row+64][k4] = ua1;
        *(uint4*)&Bs[0][row][k4]    = uw0;
        *(uint4*)&Bs[0][row+64][k4] = uw1;
    }
    __syncthreads();

    int nT = K / 16;
    int buf = 0;
    for (int t = 0; t < nT; t++) {
        if (t + 1 < nT) {
            int off = (t+1)*16;
            pa0 = *(const float4*)(Ap0 + off);
            pa1 = *(const float4*)(Ap1 + off);
            pw0 = *(const float4*)(Wp0 + off);
            pw1 = *(const float4*)(Wp1 + off);
        }
        #pragma unroll
        for (int ks = 0; ks < 2; ks++) {
            int kb = ks * 8;
            unsigned af[4][4], bf[4][2];
            #pragma unroll
            for (int mi = 0; mi < 4; mi++) {
                int r = wm*64 + mi*16 + lr;
                int c = kb + lc;
                af[mi][0] = As[buf][r  ][c];
                af[mi][1] = As[buf][r+8][c];
                af[mi][2] = As[buf][r  ][c+4];
                af[mi][3] = As[buf][r+8][c+4];
            }
            #pragma unroll
            for (int ni = 0; ni < 4; ni++) {
                int nn = wn*32 + ni*8 + lr;
                int c = kb + lc;
                bf[ni][0] = Bs[buf][nn][c];
                bf[ni][1] = Bs[buf][nn][c+4];
            }
            #pragma unroll
            for (int mi = 0; mi < 4; mi++)
                #pragma unroll
                for (int ni = 0; ni < 4; ni++)
                    mma_tf32(acc[mi][ni], af[mi], bf[ni]);
        }
        if (t + 1 < nT) {
            buf ^= 1;
            uint4 ua0 = make_uint4(f2tf(pa0.x), f2tf(pa0.y), f2tf(pa0.z), f2tf(pa0.w));
            uint4 ua1 = make_uint4(f2tf(pa1.x), f2tf(pa1.y), f2tf(pa1.z), f2tf(pa1.w));
            uint4 uw0 = make_uint4(f2tf(pw0.x), f2tf(pw0.y), f2tf(pw0.z), f2tf(pw0.w));
            uint4 uw1 = make_uint4(f2tf(pw1.x), f2tf(pw1.y), f2tf(pw1.z), f2tf(pw1.w));
            *(uint4*)&As[buf][row][k4]    = ua0;
            *(uint4*)&As[buf][row+64][k4] = ua1;
            *(uint4*)&Bs[buf][row][k4]    = uw0;
            *(uint4*)&Bs[buf][row+64][k4] = uw1;
            __syncthreads();
        }
    }

    #pragma unroll
    for (int mi = 0; mi < 4; mi++) {
        int r0 = m0 + wm*64 + mi*16 + lr;
        #pragma unroll
        for (int ni = 0; ni < 4; ni++) {
            int cb = n0 + wn*32 + ni*8 + lc*2;
            float bv0 = 0.f, bv1 = 0.f;
            if (bias) { bv0 = bias[cb]; bv1 = bias[cb+1]; }
            #pragma unroll
            for (int half = 0; half < 2; half++) {
                int r = r0 + half*8;
                float v0 = acc[mi][ni][half*2+0] + bv0;
                float v1 = acc[mi][ni][half*2+1] + bv1;
                if (EPI == 1) { v0 *= scale; v1 *= scale; }
                else if (EPI == 2) {
                    const float* Rr = res + (size_t)r*N + cb;
                    v0 += Rr[0]; v1 += Rr[1];
                }
                else if (EPI == 3) {
                    v0 = v0 / (1.f + __expf(-1.702f * v0));
                    v1 = v1 / (1.f + __expf(-1.702f * v1));
                }
                *(float2*)(C + (size_t)r*N + cb) = make_float2(v0, v1);
            }
        }
    }
}

// ---------------- te path (tiny) ----------------
__global__ __launch_bounds__(256)
void te_kernel(const float* __restrict__ te,
               const float* __restrict__ lnw, const float* __restrict__ lnb,
               const float* __restrict__ l1,  const float* __restrict__ l2,
               const float* __restrict__ ipw, const float* __restrict__ ipb,
               float* __restrict__ tek, float* __restrict__ tev)
{
    __shared__ float row[DD];
    __shared__ float lnr[DD];
    __shared__ float hb[256];
    __shared__ float hs[128];
    __shared__ float red[18];
    int t = blockIdx.x, tid = threadIdx.x;
    int lane = tid & 31, warp = tid >> 5;

    float4 v = reinterpret_cast<const float4*>(te + (size_t)t*DD)[tid];
    reinterpret_cast<float4*>(row)[tid] = v;
    float s = v.x+v.y+v.z+v.w;
    float q = v.x*v.x+v.y*v.y+v.z*v.z+v.w*v.w;
    #pragma unroll
    for (int o = 16; o; o >>= 1) {
        s += __shfl_xor_sync(0xffffffffu, s, o);
        q += __shfl_xor_sync(0xffffffffu, q, o);
    }
    if (lane == 0) { red[warp] = s; red[8+warp] = q; }
    __syncthreads();
    if (tid == 0) {
        float ss=0.f, qs=0.f;
        #pragma unroll
        for (int i=0;i<8;i++){ ss+=red[i]; qs+=red[8+i]; }
        red[16]=ss*(1.f/DD); red[17]=qs*(1.f/DD);
    }
    __syncthreads();
    float mean = red[16];
    float rs   = rsqrtf(red[17] - mean*mean + 1e-5f);
    float4 wv = reinterpret_cast<const float4*>(lnw)[tid];
    float4 bv = reinterpret_cast<const float4*>(lnb)[tid];
    float4 o4;
    o4.x=(v.x-mean)*rs*wv.x+bv.x; o4.y=(v.y-mean)*rs*wv.y+bv.y;
    o4.z=(v.z-mean)*rs*wv.z+bv.z; o4.w=(v.w-mean)*rs*wv.w+bv.w;
    reinterpret_cast<float4*>(lnr)[tid] = o4;
    __syncthreads();

    {
        int j = tid & 127, half = tid >> 7;
        const float4* wr = (const float4*)(l1 + (size_t)j*DD + half*512);
        const float4* xr = (const float4*)(lnr + half*512);
        float p = 0.f;
        #pragma unroll 8
        for (int k = 0; k < 128; k++) {
            float4 w4 = wr[k]; float4 x4 = xr[k];
            p += w4.x*x4.x + w4.y*x4.y + w4.z*x4.z + w4.w*x4.w;
        }
        hb[tid] = p;
    }
    __syncthreads();
    if (tid < 128) hs[tid] = hb[tid] + hb[tid+128];
    __syncthreads();

    float outv[4];
    #pragma unroll
    for (int ii = 0; ii < 4; ii++) {
        int i = tid + ii*256;
        const float* w2r = l2 + (size_t)i*128;
        float p = 0.f;
        #pragma unroll 8
        for (int j = 0; j < 128; j++) p += hs[j]*w2r[j];
        outv[ii] = row[i] + p;
    }
    __syncthreads();
    #pragma unroll
    for (int ii = 0; ii < 4; ii++) lnr[tid + ii*256] = outv[ii];
    __syncthreads();

    for (int o = tid; o < 2*DD; o += 256) {
        const float4* wr = (const float4*)(ipw + (size_t)(DD+o)*DD);
        float p = ipb[DD + o];
        #pragma unroll 8
        for (int d4 = 0; d4 < 256; d4++) {
            float4 w4 = wr[d4];
            float4 x4 = ((float4*)lnr)[d4];
            p += w4.x*x4.x + w4.y*x4.y + w4.z*x4.z + w4.w*x4.w;
        }
        if (o < DD) tek[(size_t)t*DD + o] = p;
        else        tev[(size_t)t*DD + (o-DD)] = p;
    }
}

// ---------------- tf32 MMA attention + conv-over-t + mean-over-t (fused) ----------------
// grid (H, N, 2), 256 threads (8 warps). Per CTA: 128 q (z-half) x (8t x 256 keys) x 64 c.
// Warp = 16 q rows, single pass. Keys chunked by 64.
// No-max softmax (score magnitudes ~sigma 1; exp overflow impossible).
// Register diet: Q frags hoisted (t-invariant), P converted in-place over S.
// Ks pitch 68 (QK B-frag perm: 4*lr+lc), Vs pitch 72 (PV B-frag perm: 8*lc+lr).
#define KPITCH 68
#define VPITCH 72
#define ATT_SMEM_WORDS (256*KPITCH + 256*VPITCH + 192)

__global__ __launch_bounds__(256, 1)
void att_mma(const float* __restrict__ sq, const float* __restrict__ ak,
             const float* __restrict__ av, const float* __restrict__ tek,
             const float* __restrict__ tev, const float* __restrict__ pm,
             const float* __restrict__ tw, const float* __restrict__ tb,
             float* __restrict__ outp)
{
    extern __shared__ unsigned sm[];
    unsigned* Ks = sm;                      // [256][68] tf32 K+te_k
    unsigned* Vs = sm + 256*KPITCH;         // [256][72] tf32 V+te_v
    float* chS  = (float*)(Vs + 256*VPITCH); // [64] (1+w0+w1+w2)/8
    float* chW0 = chS + 64;                  // [64] w0/8
    float* chW2 = chW0 + 64;                 // [64] w2/8

    int h = blockIdx.x, n = blockIdx.y;
    int qoff = blockIdx.z * 128;
    int tid = threadIdx.x, warp = tid >> 5, lane = tid & 31;
    int lr = lane >> 2, lc = lane & 3;
    int qb = qoff + warp*16;
    int quadbase = lane & ~3;

    if (tid < 64) {
        int d = h*64 + tid;
        float w0 = tw[d*3+0], w1 = tw[d*3+1], w2 = tw[d*3+2];
        chS[tid]  = (1.f + w0 + w1 + w2) * 0.125f;
        chW0[tid] = w0 * 0.125f;
        chW2[tid] = w2 * 0.125f;
    }

    // Q A-fragments, loaded once from global (t-invariant). 32 regs.
    unsigned aq[8][4];
    {
        const float* sqp = sq + (size_t)(n*QQ)*DD + h*64;
        #pragma unroll
        for (int ks = 0; ks < 8; ks++) {
            int c = ks*8 + lc;
            aq[ks][0] = f2tf(sqp[(size_t)(qb+lr  )*DD + c]);
            aq[ks][1] = f2tf(sqp[(size_t)(qb+lr+8)*DD + c]);
            aq[ks][2] = f2tf(sqp[(size_t)(qb+lr  )*DD + c+4]);
            aq[ks][3] = f2tf(sqp[(size_t)(qb+lr+8)*DD + c+4]);
        }
    }

    float acc[32];
    #pragma unroll
    for (int i = 0; i < 32; i++) acc[i] = 0.f;

    for (int t = 0; t < TT; t++) {
        __syncthreads();   // prior reads of Ks/Vs done (t=0: covers chan staging)
        const float* kb  = ak  + ((size_t)(n*TT+t)*LLEN + 1)*DD + h*64;
        const float* vb  = av  + ((size_t)(n*TT+t)*LLEN + 1)*DD + h*64;
        const float* tkp = tek + (size_t)t*DD + h*64;
        const float* tvp = tev + (size_t)t*DD + h*64;
        for (int idx = tid; idx < QQ*16; idx += 256) {
            int k = idx >> 4, c4 = (idx & 15) * 4;
            float4 kv = *(const float4*)(kb + (size_t)k*DD + c4);
            float4 tk = *(const float4*)(tkp + c4);
            *(uint4*)&Ks[k*KPITCH + c4] = make_uint4(
                f2tf(kv.x+tk.x), f2tf(kv.y+tk.y), f2tf(kv.z+tk.z), f2tf(kv.w+tk.w));
            float4 vv = *(const float4*)(vb + (size_t)k*DD + c4);
            float4 tv = *(const float4*)(tvp + c4);
            *(uint4*)&Vs[k*VPITCH + c4] = make_uint4(
                f2tf(vv.x+tv.x), f2tf(vv.y+tv.y), f2tf(vv.z+tv.z), f2tf(vv.w+tv.w));
        }
        __syncthreads();

        float curO[8][4];
        #pragma unroll
        for (int i = 0; i < 8; i++)
            #pragma unroll
            for (int f = 0; f < 4; f++) curO[i][f] = 0.f;
        float l0 = 0.f, l1 = 0.f;

        for (int chunk = 0; chunk < 4; chunk++) {
            int k0 = chunk*64;

            // S = Q @ K^T  (16q x 64k chunk); PS in-place (float view)
            float PS[8][4];
            #pragma unroll
            for (int i = 0; i < 8; i++)
                #pragma unroll
                for (int f = 0; f < 4; f++) PS[i][f] = 0.f;
            #pragma unroll
            for (int ks = 0; ks < 8; ks++) {
                #pragma unroll
                for (int nt = 0; nt < 8; nt++) {
                    unsigned bfr[2];
                    bfr[0] = Ks[(k0 + nt*8 + lr)*KPITCH + ks*8 + lc];
                    bfr[1] = Ks[(k0 + nt*8 + lr)*KPITCH + ks*8 + lc + 4];
                    mma_tf32(PS[nt], aq[ks], bfr);
                }
            }

            // mask + exp + row-sum; convert C-frag -> A-frag in place (quad shfl)
            #pragma unroll
            for (int nt = 0; nt < 8; nt++) {
                int kcol = k0 + nt*8 + 2*lc;
                const float* pmr = pm + (size_t)(qb+lr)*(LLEN-1) + kcol;
                float2 m0 = *(const float2*)pmr;
                float2 m1 = *(const float2*)(pmr + 8*(LLEN-1));
                float p0 = __expf(PS[nt][0] + m0.x);
                float p1 = __expf(PS[nt][1] + m0.y);
                float p2 = __expf(PS[nt][2] + m1.x);
                float p3 = __expf(PS[nt][3] + m1.y);
                l0 += p0 + p1;
                l1 += p2 + p3;
                int srcA = quadbase | (lc >> 1);
                int srcB = srcA + 2;
                float t0a = __shfl_sync(0xffffffffu, p0, srcA);
                float t0b = __shfl_sync(0xffffffffu, p1, srcA);
                float t2a = __shfl_sync(0xffffffffu, p0, srcB);
                float t2b = __shfl_sync(0xffffffffu, p1, srcB);
                float t1a = __shfl_sync(0xffffffffu, p2, srcA);
                float t1b = __shfl_sync(0xffffffffu, p3, srcA);
                float t3a = __shfl_sync(0xffffffffu, p2, srcB);
                float t3b = __shfl_sync(0xffffffffu, p3, srcB);
                bool odd = (lc & 1);
                PS[nt][0] = __uint_as_float(f2tf(odd ? t0b : t0a));
                PS[nt][1] = __uint_as_float(f2tf(odd ? t1b : t1a));
                PS[nt][2] = __uint_as_float(f2tf(odd ? t2b : t2a));
                PS[nt][3] = __uint_as_float(f2tf(odd ? t3b : t3a));
            }

            // curO += P @ V  (16q x 64c), keys of this chunk as k-dim
            #pragma unroll
            for (int ks = 0; ks < 8; ks++) {
                unsigned aPk[4] = {
                    __float_as_uint(PS[ks][0]), __float_as_uint(PS[ks][1]),
                    __float_as_uint(PS[ks][2]), __float_as_uint(PS[ks][3]) };
                #pragma unroll
                for (int nc = 0; nc < 8; nc++) {
                    unsigned bfr[2];
                    bfr[0] = Vs[(k0 + ks*8 + lc    )*VPITCH + nc*8 + lr];
                    bfr[1] = Vs[(k0 + ks*8 + lc + 4)*VPITCH + nc*8 + lr];
                    mma_tf32(curO[nc], aPk, bfr);
                }
            }
        } // chunks

        // finalize softmax row sums across quad
        l0 += __shfl_xor_sync(0xffffffffu, l0, 1);
        l0 += __shfl_xor_sync(0xffffffffu, l0, 2);
        l1 += __shfl_xor_sync(0xffffffffu, l1, 1);
        l1 += __shfl_xor_sync(0xffffffffu, l1, 2);
        float inv0 = 1.f / l0, inv1 = 1.f / l1;

        // acc += coef_c(t) * (1/l) * curO
        #pragma unroll
        for (int nc = 0; nc < 8; nc++) {
            int c = nc*8 + 2*lc;
            float2 cs = *(const float2*)&chS[c];
            float coef0 = cs.x, coef1 = cs.y;
            if (t == TT-1) {
                float2 w = *(const float2*)&chW0[c];
                coef0 -= w.x; coef1 -= w.y;
            }
            if (t == 0) {
                float2 w = *(const float2*)&chW2[c];
                coef0 -= w.x; coef1 -= w.y;
            }
            acc[nc*4+0] += coef0*inv0*curO[nc][0];
            acc[nc*4+1] += coef1*inv0*curO[nc][1];
            acc[nc*4+2] += coef0*inv1*curO[nc][2];
            acc[nc*4+3] += coef1*inv1*curO[nc][3];
        }
    } // t

    // epilogue: mix = acc + tconv_bias
    #pragma unroll
    for (int nc = 0; nc < 8; nc++) {
        int c = nc*8 + 2*lc;
        int d = h*64 + c;
        float2 tbv = *(const float2*)&tb[d];
        float* o0 = outp + (size_t)(n*QQ + qb + lr    )*DD + d;
        float* o1 = outp + (size_t)(n*QQ + qb + lr + 8)*DD + d;
        *(float2*)o0 = make_float2(acc[nc*4+0] + tbv.x, acc[nc*4+1] + tbv.y);
        *(float2*)o1 = make_float2(acc[nc*4+2] + tbv.x, acc[nc*4+3] + tbv.y);
    }
}

// ---------------- launch ----------------
extern "C" void kernel_launch(void* const* d_in, const int* in_sizes, int n_in,
                              void* d_out, int out_size)
{
    const float* attrs_k = (const float*)d_in[0];
    const float* attrs_v = (const float*)d_in[1];
    const float* s       = (const float*)d_in[2];
    const float* te      = (const float*)d_in[3];
    const float* pm      = (const float*)d_in[4];
    const float* ln1w    = (const float*)d_in[5];
    const float* ln1b    = (const float*)d_in[6];
    const float* ipw     = (const float*)d_in[7];
    const float* ipb     = (const float*)d_in[8];
    const float* opw     = (const float*)d_in[9];
    const float* opb     = (const float*)d_in[10];
    const float* ln2w    = (const float*)d_in[11];
    const float* ln2b    = (const float*)d_in[12];
    const float* fcw     = (const float*)d_in[13];
    const float* fcb     = (const float*)d_in[14];
    const float* pjw     = (const float*)d_in[15];
    const float* pjb     = (const float*)d_in[16];
    const float* slnw    = (const float*)d_in[17];
    const float* slnb    = (const float*)d_in[18];
    const float* sl1     = (const float*)d_in[19];
    const float* sl2     = (const float*)d_in[20];
    const float* tlnw    = (const float*)d_in[21];
    const float* tlnb    = (const float*)d_in[22];
    const float* tl1     = (const float*)d_in[23];
    const float* tl2     = (const float*)d_in[24];
    const float* tw      = (const float*)d_in[25];
    const float* tb      = (const float*)d_in[26];
    float* out = (float*)d_out;

    float *ln_buf, *h1, *sadj, *x, *sqb, *mix, *s1, *hmid, *tek, *tev;
    cudaGetSymbolAddress((void**)&ln_buf, g_ln);
    cudaGetSymbolAddress((void**)&h1,     g_h1);
    cudaGetSymbolAddress((void**)&sadj,   g_sadj);
    cudaGetSymbolAddress((void**)&x,      g_x);
    cudaGetSymbolAddress((void**)&sqb,    g_sq);
    cudaGetSymbolAddress((void**)&mix,    g_mix);
    cudaGetSymbolAddress((void**)&s1,     g_s1);
    cudaGetSymbolAddress((void**)&hmid,   g_hmid);
    cudaGetSymbolAddress((void**)&tek,    g_tek);
    cudaGetSymbolAddress((void**)&tev,    g_tev);

    static int att_smem = ATT_SMEM_WORDS * 4;
    cudaFuncSetAttribute(att_mma, cudaFuncAttributeMaxDynamicSharedMemorySize, att_smem);

    // te path (independent, tiny)
    te_kernel<<<TT, 256>>>(te, tlnw, tlnb, tl1, tl2, ipw, ipb, tek, tev);

    // s adaptor: _s = s + (LN(s) @ l1^T) @ l2^T
    ln_rows_k<<<MROWS, 256>>>(s, slnw, slnb, ln_buf);
    tgemm<0><<<dim3(1, 16), 256>>>(ln_buf, sl1, nullptr, nullptr, h1, MROWS, 128, DD, 1.f);
    tgemm<2><<<dim3(8, 16), 256>>>(h1, sl2, nullptr, s, sadj, MROWS, DD, 128, 1.f);

    // x = LN1(_s); sq = (x @ Wq^T + bq) * (1/sqrt(C))
    ln_rows_k<<<MROWS, 256>>>(sadj, ln1w, ln1b, x);
    tgemm<1><<<dim3(8, 16), 256>>>(x, ipw, ipb, nullptr, sqb, MROWS, DD, DD, 0.125f);

    // fused attention + conv-over-t + mean-over-t (tf32 MMA, q split over grid z)
    att_mma<<<dim3(HH, NB, 2), 256, att_smem>>>(sqb, attrs_k, attrs_v, tek, tev, pm, tw, tb, mix);

    // s1 = s + mix @ out_proj^T + b
    tgemm<2><<<dim3(8, 16), 256>>>(mix, opw, opb, s, s1, MROWS, DD, DD, 1.f);

    // MLP
    ln_rows_k<<<MROWS, 256>>>(s1, ln2w, ln2b, x);
    tgemm<3><<<dim3(32, 16), 256>>>(x, fcw, fcb, nullptr, hmid, MROWS, 4*DD, DD, 1.f);
    tgemm<2><<<dim3(8, 16), 256>>>(hmid, pjw, pjb, s1, out, MROWS, DD, 4*DD, 1.f);
}

// round 9
// speedup vs baseline: 1.0120x; 1.0120x over previous
#include <cuda_runtime.h>
#include <math.h>

// Problem dims (fixed)
#define NB 8
#define TT 8
#define LLEN 257
#define HH 16
#define CC 64
#define DD 1024
#define QQ 256
#define MROWS (NB*QQ)   // 2048

// ---------------- scratch (static device arrays; no allocation) ----------------
__device__ float g_ln  [MROWS*DD];
__device__ float g_h1  [MROWS*(DD/8)];
__device__ float g_sadj[MROWS*DD];
__device__ float g_x   [MROWS*DD];
__device__ float g_sq  [MROWS*DD];
__device__ float g_mix [MROWS*DD];
__device__ float g_s1  [MROWS*DD];
__device__ float g_hmid[MROWS*4*DD];
__device__ float g_tek [TT*DD];
__device__ float g_tev [TT*DD];

// ---------------- row LayerNorm ----------------
__global__ __launch_bounds__(256)
void ln_rows_k(const float* __restrict__ in, const float* __restrict__ w,
               const float* __restrict__ b, float* __restrict__ out)
{
    __shared__ float red[18];
    int r = blockIdx.x;
    int tid = threadIdx.x;
    int lane = tid & 31, warp = tid >> 5;
    float4 v = reinterpret_cast<const float4*>(in + (size_t)r*DD)[tid];
    float s = v.x + v.y + v.z + v.w;
    float q = v.x*v.x + v.y*v.y + v.z*v.z + v.w*v.w;
    #pragma unroll
    for (int o = 16; o; o >>= 1) {
        s += __shfl_xor_sync(0xffffffffu, s, o);
        q += __shfl_xor_sync(0xffffffffu, q, o);
    }
    if (lane == 0) { red[warp] = s; red[8+warp] = q; }
    __syncthreads();
    if (tid == 0) {
        float ss = 0.f, qs = 0.f;
        #pragma unroll
        for (int i = 0; i < 8; i++) { ss += red[i]; qs += red[8+i]; }
        red[16] = ss * (1.f/DD);
        red[17] = qs * (1.f/DD);
    }
    __syncthreads();
    float mean = red[16];
    float var  = red[17] - mean*mean;
    float rs   = rsqrtf(var + 1e-5f);
    float4 wv = reinterpret_cast<const float4*>(w)[tid];
    float4 bv = reinterpret_cast<const float4*>(b)[tid];
    float4 o4;
    o4.x = (v.x-mean)*rs*wv.x + bv.x;
    o4.y = (v.y-mean)*rs*wv.y + bv.y;
    o4.z = (v.z-mean)*rs*wv.z + bv.z;
    o4.w = (v.w-mean)*rs*wv.w + bv.w;
    reinterpret_cast<float4*>(out + (size_t)r*DD)[tid] = o4;
}

// ---------------- tf32 helpers ----------------
__device__ __forceinline__ unsigned f2tf(float x) {
    unsigned r;
    asm("cvt.rna.tf32.f32 %0, %1;" : "=r"(r) : "f"(x));
    return r;
}

__device__ __forceinline__ void mma_tf32(float* c, const unsigned* a, const unsigned* b) {
    asm volatile(
        "mma.sync.aligned.m16n8k8.row.col.f32.tf32.tf32.f32 "
        "{%0,%1,%2,%3},{%4,%5,%6,%7},{%8,%9},{%0,%1,%2,%3};"
        : "+f"(c[0]), "+f"(c[1]), "+f"(c[2]), "+f"(c[3])
        : "r"(a[0]), "r"(a[1]), "r"(a[2]), "r"(a[3]), "r"(b[0]), "r"(b[1]));
}

__device__ __forceinline__ void cp16(void* smem, const void* gmem) {
    unsigned sa = (unsigned)__cvta_generic_to_shared(smem);
    asm volatile("cp.async.cg.shared.global [%0], [%1], 16;" :: "r"(sa), "l"(gmem));
}

// ---------------- tf32 tensor-core GEMM: C(M,N) = A(M,K) @ W(N,K)^T ----------------
template<int EPI>
__global__ __launch_bounds__(256, 2)
void tgemm(const float* __restrict__ A, const float* __restrict__ W,
           const float* __restrict__ bias, const float* __restrict__ res,
           float* __restrict__ C, int M, int N, int K, float scale)
{
    __shared__ unsigned As[2][128][20];
    __shared__ unsigned Bs[2][128][20];

    int tid = threadIdx.x;
    int m0 = blockIdx.y * 128, n0 = blockIdx.x * 128;
    int warp = tid >> 5, lane = tid & 31;
    int wm = warp & 1, wn = warp >> 1;
    int lr = lane >> 2;
    int lc = lane & 3;

    int row = tid >> 2;
    int k4  = (tid & 3) * 4;

    const float* Ap0 = A + (size_t)(m0+row)*K + k4;
    const float* Ap1 = A + (size_t)(m0+row+64)*K + k4;
    const float* Wp0 = W + (size_t)(n0+row)*K + k4;
    const float* Wp1 = W + (size_t)(n0+row+64)*K + k4;

    float4 pa0 = *(const float4*)Ap0;
    float4 pa1 = *(const float4*)Ap1;
    float4 pw0 = *(const float4*)Wp0;
    float4 pw1 = *(const float4*)Wp1;

    float acc[4][4][4];
    #pragma unroll
    for (int mi = 0; mi < 4; mi++)
        #pragma unroll
        for (int ni = 0; ni < 4; ni++)
            #pragma unroll
            for (int f = 0; f < 4; f++) acc[mi][ni][f] = 0.f;

    {
        uint4 ua0 = make_uint4(f2tf(pa0.x), f2tf(pa0.y), f2tf(pa0.z), f2tf(pa0.w));
        uint4 ua1 = make_uint4(f2tf(pa1.x), f2tf(pa1.y), f2tf(pa1.z), f2tf(pa1.w));
        uint4 uw0 = make_uint4(f2tf(pw0.x), f2tf(pw0.y), f2tf(pw0.z), f2tf(pw0.w));
        uint4 uw1 = make_uint4(f2tf(pw1.x), f2tf(pw1.y), f2tf(pw1.z), f2tf(pw1.w));
        *(uint4*)&As[0][row][k4]    = ua0;
        *(uint4*)&As[0][row+64][k4] = ua1;
        *(uint4*)&Bs[0][row][k4]    = uw0;
        *(uint4*)&Bs[0][row+64][k4] = uw1;
    }
    __syncthreads();

    int nT = K / 16;
    int buf = 0;
    for (int t = 0; t < nT; t++) {
        if (t + 1 < nT) {
            int off = (t+1)*16;
            pa0 = *(const float4*)(Ap0 + off);
            pa1 = *(const float4*)(Ap1 + off);
            pw0 = *(const float4*)(Wp0 + off);
            pw1 = *(const float4*)(Wp1 + off);
        }
        #pragma unroll
        for (int ks = 0; ks < 2; ks++) {
            int kb = ks * 8;
            unsigned af[4][4], bf[4][2];
            #pragma unroll
            for (int mi = 0; mi < 4; mi++) {
                int r = wm*64 + mi*16 + lr;
                int c = kb + lc;
                af[mi][0] = As[buf][r  ][c];
                af[mi][1] = As[buf][r+8][c];
                af[mi][2] = As[buf][r  ][c+4];
                af[mi][3] = As[buf][r+8][c+4];
            }
            #pragma unroll
            for (int ni = 0; ni < 4; ni++) {
                int nn = wn*32 + ni*8 + lr;
                int c = kb + lc;
                bf[ni][0] = Bs[buf][nn][c];
                bf[ni][1] = Bs[buf][nn][c+4];
            }
            #pragma unroll
            for (int mi = 0; mi < 4; mi++)
                #pragma unroll
                for (int ni = 0; ni < 4; ni++)
                    mma_tf32(acc[mi][ni], af[mi], bf[ni]);
        }
        if (t + 1 < nT) {
            buf ^= 1;
            uint4 ua0 = make_uint4(f2tf(pa0.x), f2tf(pa0.y), f2tf(pa0.z), f2tf(pa0.w));
            uint4 ua1 = make_uint4(f2tf(pa1.x), f2tf(pa1.y), f2tf(pa1.z), f2tf(pa1.w));
            uint4 uw0 = make_uint4(f2tf(pw0.x), f2tf(pw0.y), f2tf(pw0.z), f2tf(pw0.w));
            uint4 uw1 = make_uint4(f2tf(pw1.x), f2tf(pw1.y), f2tf(pw1.z), f2tf(pw1.w));
            *(uint4*)&As[buf][row][k4]    = ua0;
            *(uint4*)&As[buf][row+64][k4] = ua1;
            *(uint4*)&Bs[buf][row][k4]    = uw0;
            *(uint4*)&Bs[buf][row+64][k4] = uw1;
            __syncthreads();
        }
    }

    #pragma unroll
    for (int mi = 0; mi < 4; mi++) {
        int r0 = m0 + wm*64 + mi*16 + lr;
        #pragma unroll
        for (int ni = 0; ni < 4; ni++) {
            int cb = n0 + wn*32 + ni*8 + lc*2;
            float bv0 = 0.f, bv1 = 0.f;
            if (bias) { bv0 = bias[cb]; bv1 = bias[cb+1]; }
            #pragma unroll
            for (int half = 0; half < 2; half++) {
                int r = r0 + half*8;
                float v0 = acc[mi][ni][half*2+0] + bv0;
                float v1 = acc[mi][ni][half*2+1] + bv1;
                if (EPI == 1) { v0 *= scale; v1 *= scale; }
                else if (EPI == 2) {
                    const float* Rr = res + (size_t)r*N + cb;
                    v0 += Rr[0]; v1 += Rr[1];
                }
                else if (EPI == 3) {
                    v0 = v0 / (1.f + __expf(-1.702f * v0));
                    v1 = v1 / (1.f + __expf(-1.702f * v1));
                }
                *(float2*)(C + (size_t)r*N + cb) = make_float2(v0, v1);
            }
        }
    }
}

// ---------------- te path (tiny) ----------------
__global__ __launch_bounds__(256)
void te_kernel(const float* __restrict__ te,
               const float* __restrict__ lnw, const float* __restrict__ lnb,
               const float* __restrict__ l1,  const float* __restrict__ l2,
               const float* __restrict__ ipw, const float* __restrict__ ipb,
               float* __restrict__ tek, float* __restrict__ tev)
{
    __shared__ float row[DD];
    __shared__ float lnr[DD];
    __shared__ float hb[256];
    __shared__ float hs[128];
    __shared__ float red[18];
    int t = blockIdx.x, tid = threadIdx.x;
    int lane = tid & 31, warp = tid >> 5;

    float4 v = reinterpret_cast<const float4*>(te + (size_t)t*DD)[tid];
    reinterpret_cast<float4*>(row)[tid] = v;
    float s = v.x+v.y+v.z+v.w;
    float q = v.x*v.x+v.y*v.y+v.z*v.z+v.w*v.w;
    #pragma unroll
    for (int o = 16; o; o >>= 1) {
        s += __shfl_xor_sync(0xffffffffu, s, o);
        q += __shfl_xor_sync(0xffffffffu, q, o);
    }
    if (lane == 0) { red[warp] = s; red[8+warp] = q; }
    __syncthreads();
    if (tid == 0) {
        float ss=0.f, qs=0.f;
        #pragma unroll
        for (int i=0;i<8;i++){ ss+=red[i]; qs+=red[8+i]; }
        red[16]=ss*(1.f/DD); red[17]=qs*(1.f/DD);
    }
    __syncthreads();
    float mean = red[16];
    float rs   = rsqrtf(red[17] - mean*mean + 1e-5f);
    float4 wv = reinterpret_cast<const float4*>(lnw)[tid];
    float4 bv = reinterpret_cast<const float4*>(lnb)[tid];
    float4 o4;
    o4.x=(v.x-mean)*rs*wv.x+bv.x; o4.y=(v.y-mean)*rs*wv.y+bv.y;
    o4.z=(v.z-mean)*rs*wv.z+bv.z; o4.w=(v.w-mean)*rs*wv.w+bv.w;
    reinterpret_cast<float4*>(lnr)[tid] = o4;
    __syncthreads();

    {
        int j = tid & 127, half = tid >> 7;
        const float4* wr = (const float4*)(l1 + (size_t)j*DD + half*512);
        const float4* xr = (const float4*)(lnr + half*512);
        float p = 0.f;
        #pragma unroll 8
        for (int k = 0; k < 128; k++) {
            float4 w4 = wr[k]; float4 x4 = xr[k];
            p += w4.x*x4.x + w4.y*x4.y + w4.z*x4.z + w4.w*x4.w;
        }
        hb[tid] = p;
    }
    __syncthreads();
    if (tid < 128) hs[tid] = hb[tid] + hb[tid+128];
    __syncthreads();

    float outv[4];
    #pragma unroll
    for (int ii = 0; ii < 4; ii++) {
        int i = tid + ii*256;
        const float* w2r = l2 + (size_t)i*128;
        float p = 0.f;
        #pragma unroll 8
        for (int j = 0; j < 128; j++) p += hs[j]*w2r[j];
        outv[ii] = row[i] + p;
    }
    __syncthreads();
    #pragma unroll
    for (int ii = 0; ii < 4; ii++) lnr[tid + ii*256] = outv[ii];
    __syncthreads();

    for (int o = tid; o < 2*DD; o += 256) {
        const float4* wr = (const float4*)(ipw + (size_t)(DD+o)*DD);
        float p = ipb[DD + o];
        #pragma unroll 8
        for (int d4 = 0; d4 < 256; d4++) {
            float4 w4 = wr[d4];
            float4 x4 = ((float4*)lnr)[d4];
            p += w4.x*x4.x + w4.y*x4.y + w4.z*x4.z + w4.w*x4.w;
        }
        if (o < DD) tek[(size_t)t*DD + o] = p;
        else        tev[(size_t)t*DD + (o-DD)] = p;
    }
}

// ---------------- tf32 MMA attention + conv-over-t + mean-over-t (fused) ----------------
// grid (H, N, 2), 256 threads (8 warps). Per CTA: 128 q x (8t x 256 keys) x 64 c.
// te_k/te_v handled ALGEBRAICALLY:
//   Q·(K+teK) = Q·K + bias[q,t],  softmax·(V+teV) = (P·V)/l + teV[t,:]
// so K/V staging is a PURE COPY -> cp.async double-buffered 128-key stages,
// fully overlapped with MMA compute. MMA consumes raw fp32 bits as tf32.
#define KP 68   // K pitch: QK B-frag bank pattern 4*lr+lc = permutation
#define VP 72   // V pitch: PV B-frag bank pattern 8*lc+lr = permutation
#define STRIDE_BUF (128*KP + 128*VP)
#define ATT_SMEM_WORDS (2*STRIDE_BUF + 512 + 512 + 192)

__global__ __launch_bounds__(256, 1)
void att_mma(const float* __restrict__ sq, const float* __restrict__ ak,
             const float* __restrict__ av, const float* __restrict__ tek,
             const float* __restrict__ tev, const float* __restrict__ pm,
             const float* __restrict__ tw, const float* __restrict__ tb,
             float* __restrict__ outp)
{
    extern __shared__ unsigned sm[];
    // buffers: [buf] { K[128][KP], V[128][VP] }
    float* tek_s = (float*)(sm + 2*STRIDE_BUF);        // [8][64]
    float* tev_s = tek_s + 512;                        // [8][64]
    float* chS   = tev_s + 512;                        // [64]
    float* chW0  = chS + 64;
    float* chW2  = chW0 + 64;

    int h = blockIdx.x, n = blockIdx.y;
    int qoff = blockIdx.z * 128;
    int tid = threadIdx.x, warp = tid >> 5, lane = tid & 31;
    int lr = lane >> 2, lc = lane & 3;
    int qb = qoff + warp*16;

    // stage small constants to smem
    if (tid < 64) {
        int d = h*64 + tid;
        float w0 = tw[d*3+0], w1 = tw[d*3+1], w2 = tw[d*3+2];
        chS[tid]  = (1.f + w0 + w1 + w2) * 0.125f;
        chW0[tid] = w0 * 0.125f;
        chW2[tid] = w2 * 0.125f;
    }
    for (int i = tid; i < 512; i += 256) {
        tek_s[i] = tek[(i >> 6)*DD + h*64 + (i & 63)];
        tev_s[i] = tev[(i >> 6)*DD + h*64 + (i & 63)];
    }

    // Q A-fragments (t-invariant), tf32-rounded
    unsigned aq[8][4];
    {
        const float* sqp = sq + (size_t)(n*QQ)*DD + h*64;
        #pragma unroll
        for (int ks = 0; ks < 8; ks++) {
            int c = ks*8 + lc;
            aq[ks][0] = f2tf(sqp[(size_t)(qb+lr  )*DD + c]);
            aq[ks][1] = f2tf(sqp[(size_t)(qb+lr+8)*DD + c]);
            aq[ks][2] = f2tf(sqp[(size_t)(qb+lr  )*DD + c+4]);
            aq[ks][3] = f2tf(sqp[(size_t)(qb+lr+8)*DD + c+4]);
        }
    }

    const float* akb = ak + ((size_t)(n*TT)*LLEN + 1)*DD + h*64;
    const float* avb = av + ((size_t)(n*TT)*LLEN + 1)*DD + h*64;

    // stage loader: stage s -> t = s>>1, keys [(s&1)*128, +128)
    auto load_stage = [&](int s) {
        int t = s >> 1, half = s & 1;
        int buf = s & 1;  // stage parity == buffer parity (16 stages, alternating)
        unsigned* Kbuf = sm + buf*STRIDE_BUF;
        unsigned* Vbuf = Kbuf + 128*KP;
        const float* kb = akb + (size_t)t*LLEN*DD + (size_t)half*128*DD;
        const float* vb = avb + (size_t)t*LLEN*DD + (size_t)half*128*DD;
        #pragma unroll
        for (int i = 0; i < 8; i++) {
            int idx = tid + i*256;          // 0..2047
            int k = idx >> 4, c4 = (idx & 15) * 4;
            cp16(&Kbuf[k*KP + c4], kb + (size_t)k*DD + c4);
            cp16(&Vbuf[k*VP + c4], vb + (size_t)k*DD + c4);
        }
    };

    float acc[32];
    #pragma unroll
    for (int i = 0; i < 32; i++) acc[i] = 0.f;

    load_stage(0);
    asm volatile("cp.async.commit_group;");

    float curO[8][4];
    float l0 = 0.f, l1 = 0.f;
    float biasA = 0.f, biasB = 0.f;

    for (int s = 0; s < 16; s++) {
        int t = s >> 1, half = s & 1;
        int buf = s & 1;
        unsigned* Kbuf = sm + buf*STRIDE_BUF;
        unsigned* Vbuf = Kbuf + 128*KP;

        if (s < 15) {
            load_stage(s + 1);
            asm volatile("cp.async.commit_group;");
            asm volatile("cp.async.wait_group 1;");
        } else {
            asm volatile("cp.async.wait_group 0;");
        }
        __syncthreads();

        if (half == 0) {
            #pragma unroll
            for (int i = 0; i < 8; i++)
                #pragma unroll
                for (int f = 0; f < 4; f++) curO[i][f] = 0.f;
            l0 = 0.f; l1 = 0.f;
            // score bias for this t: dot(sq_row, te_k[t]) via aq frags + quad reduce
            float pA = 0.f, pB = 0.f;
            #pragma unroll
            for (int ks = 0; ks < 8; ks++) {
                float ta = tek_s[t*64 + ks*8 + lc];
                float tb4 = tek_s[t*64 + ks*8 + lc + 4];
                pA += __uint_as_float(aq[ks][0])*ta + __uint_as_float(aq[ks][2])*tb4;
                pB += __uint_as_float(aq[ks][1])*ta + __uint_as_float(aq[ks][3])*tb4;
            }
            pA += __shfl_xor_sync(0xffffffffu, pA, 1);
            pA += __shfl_xor_sync(0xffffffffu, pA, 2);
            pB += __shfl_xor_sync(0xffffffffu, pB, 1);
            pB += __shfl_xor_sync(0xffffffffu, pB, 2);
            biasA = pA; biasB = pB;
        }

        #pragma unroll
        for (int chunk = 0; chunk < 2; chunk++) {
            int k0 = chunk*64;

            float PS[8][4];
            #pragma unroll
            for (int i = 0; i < 8; i++)
                #pragma unroll
                for (int f = 0; f < 4; f++) PS[i][f] = 0.f;

            #pragma unroll
            for (int ks = 0; ks < 8; ks++) {
                unsigned bfr[8][2];
                #pragma unroll
                for (int nt = 0; nt < 8; nt++) {
                    bfr[nt][0] = Kbuf[(k0 + nt*8 + lr)*KP + ks*8 + lc];
                    bfr[nt][1] = Kbuf[(k0 + nt*8 + lr)*KP + ks*8 + lc + 4];
                }
                #pragma unroll
                for (int nt = 0; nt < 8; nt++)
                    mma_tf32(PS[nt], aq[ks], bfr[nt]);
            }

            int quadbase = lane & ~3;
            #pragma unroll
            for (int nt = 0; nt < 8; nt++) {
                int kcol = half*128 + k0 + nt*8 + 2*lc;
                const float* pmr = pm + (size_t)(qb+lr)*(LLEN-1) + kcol;
                float2 m0 = *(const float2*)pmr;
                float2 m1 = *(const float2*)(pmr + 8*(LLEN-1));
                float p0 = __expf(PS[nt][0] + m0.x + biasA);
                float p1 = __expf(PS[nt][1] + m0.y + biasA);
                float p2 = __expf(PS[nt][2] + m1.x + biasB);
                float p3 = __expf(PS[nt][3] + m1.y + biasB);
                l0 += p0 + p1;
                l1 += p2 + p3;
                int srcA = quadbase | (lc >> 1);
                int srcB = srcA + 2;
                float t0a = __shfl_sync(0xffffffffu, p0, srcA);
                float t0b = __shfl_sync(0xffffffffu, p1, srcA);
                float t2a = __shfl_sync(0xffffffffu, p0, srcB);
                float t2b = __shfl_sync(0xffffffffu, p1, srcB);
                float t1a = __shfl_sync(0xffffffffu, p2, srcA);
                float t1b = __shfl_sync(0xffffffffu, p3, srcA);
                float t3a = __shfl_sync(0xffffffffu, p2, srcB);
                float t3b = __shfl_sync(0xffffffffu, p3, srcB);
                bool odd = (lc & 1);
                PS[nt][0] = __uint_as_float(f2tf(odd ? t0b : t0a));
                PS[nt][1] = __uint_as_float(f2tf(odd ? t1b : t1a));
                PS[nt][2] = __uint_as_float(f2tf(odd ? t2b : t2a));
                PS[nt][3] = __uint_as_float(f2tf(odd ? t3b : t3a));
            }

            #pragma unroll
            for (int ks = 0; ks < 8; ks++) {
                unsigned aPk[4] = {
                    __float_as_uint(PS[ks][0]), __float_as_uint(PS[ks][1]),
                    __float_as_uint(PS[ks][2]), __float_as_uint(PS[ks][3]) };
                unsigned bv[8][2];
                #pragma unroll
                for (int nc = 0; nc < 8; nc++) {
                    bv[nc][0] = Vbuf[(k0 + ks*8 + lc    )*VP + nc*8 + lr];
                    bv[nc][1] = Vbuf[(k0 + ks*8 + lc + 4)*VP + nc*8 + lr];
                }
                #pragma unroll
                for (int nc = 0; nc < 8; nc++)
                    mma_tf32(curO[nc], aPk, bv[nc]);
            }
        } // chunks
        __syncthreads();

        if (half == 1) {
            l0 += __shfl_xor_sync(0xffffffffu, l0, 1);
            l0 += __shfl_xor_sync(0xffffffffu, l0, 2);
            l1 += __shfl_xor_sync(0xffffffffu, l1, 1);
            l1 += __shfl_xor_sync(0xffffffffu, l1, 2);
            float inv0 = 1.f / l0, inv1 = 1.f / l1;

            #pragma unroll
            for (int nc = 0; nc < 8; nc++) {
                int c = nc*8 + 2*lc;
                float2 cs = *(const float2*)&chS[c];
                float coef0 = cs.x, coef1 = cs.y;
                if (t == TT-1) {
                    float2 w = *(const float2*)&chW0[c];
                    coef0 -= w.x; coef1 -= w.y;
                }
                if (t == 0) {
                    float2 w = *(const float2*)&chW2[c];
                    coef0 -= w.x; coef1 -= w.y;
                }
                float2 tv = *(const float2*)&tev_s[t*64 + c];
                acc[nc*4+0] += coef0*(inv0*curO[nc][0] + tv.x);
                acc[nc*4+1] += coef1*(inv0*curO[nc][1] + tv.y);
                acc[nc*4+2] += coef0*(inv1*curO[nc][2] + tv.x);
                acc[nc*4+3] += coef1*(inv1*curO[nc][3] + tv.y);
            }
        }
    } // stages

    // epilogue: mix = acc + tconv_bias
    #pragma unroll
    for (int nc = 0; nc < 8; nc++) {
        int c = nc*8 + 2*lc;
        int d = h*64 + c;
        float2 tbv = *(const float2*)&tb[d];
        float* o0 = outp + (size_t)(n*QQ + qb + lr    )*DD + d;
        float* o1 = outp + (size_t)(n*QQ + qb + lr + 8)*DD + d;
        *(float2*)o0 = make_float2(acc[nc*4+0] + tbv.x, acc[nc*4+1] + tbv.y);
        *(float2*)o1 = make_float2(acc[nc*4+2] + tbv.x, acc[nc*4+3] + tbv.y);
    }
}

// ---------------- launch ----------------
extern "C" void kernel_launch(void* const* d_in, const int* in_sizes, int n_in,
                              void* d_out, int out_size)
{
    const float* attrs_k = (const float*)d_in[0];
    const float* attrs_v = (const float*)d_in[1];
    const float* s       = (const float*)d_in[2];
    const float* te      = (const float*)d_in[3];
    const float* pm      = (const float*)d_in[4];
    const float* ln1w    = (const float*)d_in[5];
    const float* ln1b    = (const float*)d_in[6];
    const float* ipw     = (const float*)d_in[7];
    const float* ipb     = (const float*)d_in[8];
    const float* opw     = (const float*)d_in[9];
    const float* opb     = (const float*)d_in[10];
    const float* ln2w    = (const float*)d_in[11];
    const float* ln2b    = (const float*)d_in[12];
    const float* fcw     = (const float*)d_in[13];
    const float* fcb     = (const float*)d_in[14];
    const float* pjw     = (const float*)d_in[15];
    const float* pjb     = (const float*)d_in[16];
    const float* slnw    = (const float*)d_in[17];
    const float* slnb    = (const float*)d_in[18];
    const float* sl1     = (const float*)d_in[19];
    const float* sl2     = (const float*)d_in[20];
    const float* tlnw    = (const float*)d_in[21];
    const float* tlnb    = (const float*)d_in[22];
    const float* tl1     = (const float*)d_in[23];
    const float* tl2     = (const float*)d_in[24];
    const float* tw      = (const float*)d_in[25];
    const float* tb      = (const float*)d_in[26];
    float* out = (float*)d_out;

    float *ln_buf, *h1, *sadj, *x, *sqb, *mix, *s1, *hmid, *tek, *tev;
    cudaGetSymbolAddress((void**)&ln_buf, g_ln);
    cudaGetSymbolAddress((void**)&h1,     g_h1);
    cudaGetSymbolAddress((void**)&sadj,   g_sadj);
    cudaGetSymbolAddress((void**)&x,      g_x);
    cudaGetSymbolAddress((void**)&sqb,    g_sq);
    cudaGetSymbolAddress((void**)&mix,    g_mix);
    cudaGetSymbolAddress((void**)&s1,     g_s1);
    cudaGetSymbolAddress((void**)&hmid,   g_hmid);
    cudaGetSymbolAddress((void**)&tek,    g_tek);
    cudaGetSymbolAddress((void**)&tev,    g_tev);

    static int att_smem = ATT_SMEM_WORDS * 4;
    cudaFuncSetAttribute(att_mma, cudaFuncAttributeMaxDynamicSharedMemorySize, att_smem);

    // te path (independent, tiny)
    te_kernel<<<TT, 256>>>(te, tlnw, tlnb, tl1, tl2, ipw, ipb, tek, tev);

    // s adaptor: _s = s + (LN(s) @ l1^T) @ l2^T
    ln_rows_k<<<MROWS, 256>>>(s, slnw, slnb, ln_buf);
    tgemm<0><<<dim3(1, 16), 256>>>(ln_buf, sl1, nullptr, nullptr, h1, MROWS, 128, DD, 1.f);
    tgemm<2><<<dim3(8, 16), 256>>>(h1, sl2, nullptr, s, sadj, MROWS, DD, 128, 1.f);

    // x = LN1(_s); sq = (x @ Wq^T + bq) * (1/sqrt(C))
    ln_rows_k<<<MROWS, 256>>>(sadj, ln1w, ln1b, x);
    tgemm<1><<<dim3(8, 16), 256>>>(x, ipw, ipb, nullptr, sqb, MROWS, DD, DD, 0.125f);

    // fused attention + conv-over-t + mean-over-t (tf32 MMA, cp.async pipelined)
    att_mma<<<dim3(HH, NB, 2), 256, att_smem>>>(sqb, attrs_k, attrs_v, tek, tev, pm, tw, tb, mix);

    // s1 = s + mix @ out_proj^T + b
    tgemm<2><<<dim3(8, 16), 256>>>(mix, opw, opb, s, s1, MROWS, DD, DD, 1.f);

    // MLP
    ln_rows_k<<<MROWS, 256>>>(s1, ln2w, ln2b, x);
    tgemm<3><<<dim3(32, 16), 256>>>(x, fcw, fcb, nullptr, hmid, MROWS, 4*DD, DD, 1.f);
    tgemm<2><<<dim3(8, 16), 256>>>(hmid, pjw, pjb, s1, out, MROWS, DD, 4*DD, 1.f);
}